// round 17
// baseline (speedup 1.0000x reference)
#include <cuda_runtime.h>
#include <cstdint>

// Problem constants
#define NN 20000          // nodes
#define NE 100000         // edges
#define HID 512
#define G3 1536           // 3*HID
#define NH 8              // heads
#define OD 64             // out dim per head

// ---------------- scratch (device globals; no allocation allowed) ----------
__device__ __align__(16) float g_GI [(size_t)NN * G3];
__device__ __align__(16) float g_H1 [(size_t)NN * HID];
__device__ __align__(16) float g_GH2[(size_t)NN * G3];
__device__ __align__(16) float g_h2 [(size_t)NE * HID];
__device__ __align__(16) float g_GH3[(size_t)NE * G3];
__device__ __align__(16) float g_h3 [(size_t)NE * HID];
__device__ float    g_a   [NE * NH];
__device__ float    g_ea  [NE * NH];
__device__ unsigned g_amax[NN * NH];
__device__ float    g_den [NN * NH];

// ---------------- helpers ---------------------------------------------------
__device__ __forceinline__ float sigmoidf(float x) { return 1.0f / (1.0f + expf(-x)); }

__device__ __forceinline__ unsigned f2o(float f) {
    unsigned u = __float_as_uint(f);
    return (u & 0x80000000u) ? ~u : (u | 0x80000000u);
}
__device__ __forceinline__ float o2f(unsigned u) {
    return __uint_as_float((u & 0x80000000u) ? (u ^ 0x80000000u) : ~u);
}
__device__ __forceinline__ uint32_t f2tf32(float f) {
    uint32_t r;
    asm("cvt.rna.tf32.f32 %0, %1;" : "=r"(r) : "f"(f));
    return r;
}
__device__ __forceinline__ void mma_tf32(float c[4],
                                         uint32_t a0, uint32_t a1, uint32_t a2, uint32_t a3,
                                         uint32_t b0, uint32_t b1) {
    asm volatile(
        "mma.sync.aligned.m16n8k8.row.col.f32.tf32.tf32.f32 "
        "{%0,%1,%2,%3}, {%4,%5,%6,%7}, {%8,%9}, {%0,%1,%2,%3};"
        : "+f"(c[0]), "+f"(c[1]), "+f"(c[2]), "+f"(c[3])
        : "r"(a0), "r"(a1), "r"(a2), "r"(a3), "r"(b0), "r"(b1));
}

// ---------------- init ------------------------------------------------------
__global__ void init_kernel(float* __restrict__ out) {
    int i = blockIdx.x * blockDim.x + threadIdx.x;
    if (i < NN * HID) out[i] = 0.0f;
    if (i < NN * NH) { g_den[i] = 0.0f; g_amax[i] = 0x007FFFFFu; /* f2o(-inf) */ }
}

// ---------------- TF32 mma.sync GEMM: C[M,1536] = A[M,K] @ B[1536,K]^T + bias
// CTA tile 128x256, BK=16, 8 warps (2x4) of 64x64 warp tiles.
// smem layout: per row (16 k-values) stored column-permuted so that the pair
// (k, k+4) needed by one mma thread is adjacent -> conflict-free LDS.64.
//   pos(c) = (c&3)*2 + ((c>>2)&1) + ((c>>3)<<3),  row stride 24 words.
#define BM 128
#define BN 256
#define BK 16
#define RST 24                       // words per smem row
#define A_WORDS (BM * RST)           // 3072
#define B_WORDS (BN * RST)           // 6144
#define GEMM_SMEM ((2 * (A_WORDS + B_WORDS)) * 4)   // 73728 bytes

__global__ __launch_bounds__(256)
void tc_gemm2(const float* __restrict__ A, int lda,
              const float* __restrict__ B,        // [1536, K] row-major
              const float* __restrict__ bias,     // [1536]
              float* __restrict__ C,              // [M, 1536]
              int M, int K)
{
    extern __shared__ uint32_t sm[];
    // word offsets: As[2] then Bs[2]
    const int AS_OFF[2] = {0, A_WORDS};
    const int BS_OFF[2] = {2 * A_WORDS, 2 * A_WORDS + B_WORDS};

    const int tid  = threadIdx.x;
    const int lane = tid & 31;
    const int warp = tid >> 5;
    const int gq = lane >> 2;          // 0..7
    const int gc = lane & 3;           // 0..3
    const int wm = (warp >> 2) * 64;   // 0 or 64
    const int wn = (warp & 3) * 64;    // 0,64,128,192
    const int m0 = blockIdx.y * BM;
    const int n0 = blockIdx.x * BN;
    const int kt = K / BK;

    float acc[4][8][4];
#pragma unroll
    for (int mi = 0; mi < 4; mi++)
#pragma unroll
        for (int ni = 0; ni < 8; ni++)
#pragma unroll
            for (int r = 0; r < 4; r++) acc[mi][ni][r] = 0.0f;

    // staging assignment: thread handles A rows (rA, rA+64), B rows rA+i*64
    const int rA   = tid >> 2;               // 0..63
    const int c4   = (tid & 3) * 4;          // 0,4,8,12
    const int posb = ((c4 >> 2) & 1) + ((c4 >> 3) << 3);  // 0,1,8,9
    int gmA0 = m0 + rA;      if (gmA0 >= M) gmA0 = M - 1;  // clamp; stores guarded
    int gmA1 = m0 + rA + 64; if (gmA1 >= M) gmA1 = M - 1;

    float4 pa0, pa1, pb0, pb1, pb2, pb3;

#define GLOAD(k0)                                                               \
    do {                                                                        \
        pa0 = *reinterpret_cast<const float4*>(&A[(size_t)gmA0 * lda + (k0) + c4]); \
        pa1 = *reinterpret_cast<const float4*>(&A[(size_t)gmA1 * lda + (k0) + c4]); \
        pb0 = *reinterpret_cast<const float4*>(&B[(size_t)(n0 + rA      ) * K + (k0) + c4]); \
        pb1 = *reinterpret_cast<const float4*>(&B[(size_t)(n0 + rA +  64) * K + (k0) + c4]); \
        pb2 = *reinterpret_cast<const float4*>(&B[(size_t)(n0 + rA + 128) * K + (k0) + c4]); \
        pb3 = *reinterpret_cast<const float4*>(&B[(size_t)(n0 + rA + 192) * K + (k0) + c4]); \
    } while (0)

#define STS1(base, row, v)                                                      \
    do {                                                                        \
        uint32_t* p = sm + (base) + (row) * RST + posb;                         \
        p[0] = f2tf32((v).x); p[2] = f2tf32((v).y);                             \
        p[4] = f2tf32((v).z); p[6] = f2tf32((v).w);                             \
    } while (0)

#define STS(buf)                                                                \
    do {                                                                        \
        STS1(AS_OFF[buf], rA,       pa0);                                       \
        STS1(AS_OFF[buf], rA + 64,  pa1);                                       \
        STS1(BS_OFF[buf], rA,       pb0);                                       \
        STS1(BS_OFF[buf], rA + 64,  pb1);                                       \
        STS1(BS_OFF[buf], rA + 128, pb2);                                       \
        STS1(BS_OFF[buf], rA + 192, pb3);                                       \
    } while (0)

    GLOAD(0);
    STS(0);
    __syncthreads();

#pragma unroll 1
    for (int t = 0; t < kt; t++) {
        if (t + 1 < kt) GLOAD((t + 1) * BK);

        const uint32_t* as = sm + AS_OFF[t & 1];
        const uint32_t* bs = sm + BS_OFF[t & 1];
#pragma unroll
        for (int kk = 0; kk < 2; kk++) {
            const int ko = gc * 2 + kk * 8;
            uint32_t a[4][4];
#pragma unroll
            for (int mi = 0; mi < 4; mi++) {
                const int r0 = wm + mi * 16 + gq;
                uint2 lo = *reinterpret_cast<const uint2*>(&as[r0 * RST + ko]);
                uint2 hi = *reinterpret_cast<const uint2*>(&as[(r0 + 8) * RST + ko]);
                a[mi][0] = lo.x; a[mi][1] = hi.x; a[mi][2] = lo.y; a[mi][3] = hi.y;
            }
#pragma unroll
            for (int ni = 0; ni < 8; ni++) {
                const int rb = wn + ni * 8 + gq;
                uint2 b = *reinterpret_cast<const uint2*>(&bs[rb * RST + ko]);
#pragma unroll
                for (int mi = 0; mi < 4; mi++)
                    mma_tf32(acc[mi][ni], a[mi][0], a[mi][1], a[mi][2], a[mi][3],
                             b.x, b.y);
            }
        }

        if (t + 1 < kt) {
            STS((t + 1) & 1);
            __syncthreads();
        }
    }

    // epilogue: bias add, guarded float2 stores
#pragma unroll
    for (int mi = 0; mi < 4; mi++) {
        const int r = m0 + wm + mi * 16 + gq;
#pragma unroll
        for (int ni = 0; ni < 8; ni++) {
            const int c = n0 + wn + ni * 8 + gc * 2;
            const float b0 = bias[c], b1 = bias[c + 1];
            if (r < M)
                *reinterpret_cast<float2*>(&C[(size_t)r * G3 + c]) =
                    make_float2(acc[mi][ni][0] + b0, acc[mi][ni][1] + b1);
            if (r + 8 < M)
                *reinterpret_cast<float2*>(&C[(size_t)(r + 8) * G3 + c]) =
                    make_float2(acc[mi][ni][2] + b0, acc[mi][ni][3] + b1);
        }
    }
#undef GLOAD
#undef STS1
#undef STS
}

// ---------------- step 1 (per node): h1 from GI and b_hh --------------------
__global__ void h1_kernel(const float* __restrict__ b_hh) {
    int i = blockIdx.x * blockDim.x + threadIdx.x;
    if (i >= NN * HID) return;
    int n = i / HID, d = i % HID;
    const float* gi = g_GI + (size_t)n * G3;
    float r  = sigmoidf(gi[d]           + b_hh[d]);
    float z  = sigmoidf(gi[HID + d]     + b_hh[HID + d]);
    float nn = tanhf   (gi[2 * HID + d] + r * b_hh[2 * HID + d]);
    g_H1[(size_t)n * HID + d] = (1.0f - z) * nn;   // h0 = 0
}

// ---------------- step 2 (per edge): pure gather + elementwise --------------
__global__ void h2_kernel(const int* __restrict__ emi) {
    int e = blockIdx.x;
    int d = threadIdx.x;
    int i0 = emi[e * 3 + 0];
    int i1 = emi[e * 3 + 1];
    const float* gi = g_GI  + (size_t)i1 * G3;
    const float* gh = g_GH2 + (size_t)i0 * G3;
    float r  = sigmoidf(gi[d]           + gh[d]);
    float z  = sigmoidf(gi[HID + d]     + gh[HID + d]);
    float nn = tanhf   (gi[2 * HID + d] + r * gh[2 * HID + d]);
    float hp = g_H1[(size_t)i0 * HID + d];
    g_h2[(size_t)e * HID + d] = (1.0f - z) * nn + z * hp;
}

// ---------------- step 3 fused with attention logits + segment max ----------
__global__ void h3_attn_kernel(const int* __restrict__ emi,
                               const float* __restrict__ attn,
                               const int* __restrict__ edge_dst) {
    __shared__ float part[16];
    int e = blockIdx.x;
    int d = threadIdx.x;
    int i2 = emi[e * 3 + 2];
    const float* gi = g_GI  + (size_t)i2 * G3;
    const float* gh = g_GH3 + (size_t)e  * G3;
    float r  = sigmoidf(gi[d]           + gh[d]);
    float z  = sigmoidf(gi[HID + d]     + gh[HID + d]);
    float nn = tanhf   (gi[2 * HID + d] + r * gh[2 * HID + d]);
    float hp = g_h2[(size_t)e * HID + d];
    float h3 = (1.0f - z) * nn + z * hp;
    g_h3[(size_t)e * HID + d] = h3;
    float v = h3 * attn[d];     // attn flattened [8*64] aligns with d
#pragma unroll
    for (int o = 16; o > 0; o >>= 1) v += __shfl_xor_sync(0xffffffffu, v, o);
    if ((d & 31) == 0) part[d >> 5] = v;
    __syncthreads();
    if (d < NH) {
        float a = part[2 * d] + part[2 * d + 1];
        a = (a >= 0.0f) ? a : 0.01f * a;
        g_a[e * NH + d] = a;
        atomicMax(&g_amax[edge_dst[e] * NH + d], f2o(a));
    }
}

// ---------------- exp + segment sum ------------------------------------------
__global__ void expsum_kernel(const int* __restrict__ edge_dst) {
    int i = blockIdx.x * blockDim.x + threadIdx.x;
    if (i >= NE * NH) return;
    int e = i >> 3, h = i & 7;
    int dst = edge_dst[e];
    float m = o2f(g_amax[dst * NH + h]);
    float ea = expf(g_a[i] - m);
    g_ea[i] = ea;
    atomicAdd(&g_den[dst * NH + h], ea);
}

// ---------------- weighted aggregation ---------------------------------------
__global__ void agg_kernel(const int* __restrict__ edge_dst,
                           float* __restrict__ out) {
    int e = blockIdx.x;
    int j = threadIdx.x;
    int h = j >> 6;
    int dst = edge_dst[e];
    float alpha = g_ea[e * NH + h] / g_den[dst * NH + h];
    atomicAdd(&out[(size_t)dst * HID + j], g_h3[(size_t)e * HID + j] * alpha);
}

// ---------------- launcher ----------------------------------------------------
extern "C" void kernel_launch(void* const* d_in, const int* in_sizes, int n_in,
                              void* d_out, int out_size) {
    const float* features = (const float*)d_in[0];   // [20000, 64]
    const float* W_ih     = (const float*)d_in[1];   // [1536, 64]
    const float* W_hh     = (const float*)d_in[2];   // [1536, 512]
    const float* b_ih     = (const float*)d_in[3];   // [1536]
    const float* b_hh     = (const float*)d_in[4];   // [1536]
    const float* attn     = (const float*)d_in[5];   // [8, 64]
    const int*   emi      = (const int*)  d_in[6];   // [100000, 3]
    const int*   edge_dst = (const int*)  d_in[7];   // [100000]
    float* out = (float*)d_out;                      // [20000, 8, 64]

    float *GI, *H1, *GH2, *h2, *GH3;
    cudaGetSymbolAddress((void**)&GI,  g_GI);
    cudaGetSymbolAddress((void**)&H1,  g_H1);
    cudaGetSymbolAddress((void**)&GH2, g_GH2);
    cudaGetSymbolAddress((void**)&h2,  g_h2);
    cudaGetSymbolAddress((void**)&GH3, g_GH3);

    cudaFuncSetAttribute(tc_gemm2, cudaFuncAttributeMaxDynamicSharedMemorySize, GEMM_SMEM);

    // 0. init output / softmax accumulators
    init_kernel<<<(NN * HID + 255) / 256, 256>>>(out);

    const int gx = G3 / BN;   // 6
    // 1. GI = features @ W_ih^T + b_ih   (per node, K=64)
    tc_gemm2<<<dim3(gx, (NN + BM - 1) / BM), 256, GEMM_SMEM>>>(features, OD, W_ih, b_ih, GI, NN, OD);
    // 2. H1 per node
    h1_kernel<<<(NN * HID + 255) / 256, 256>>>(b_hh);
    // 3. GH2 = H1 @ W_hh^T + b_hh        (per node, K=512)
    tc_gemm2<<<dim3(gx, (NN + BM - 1) / BM), 256, GEMM_SMEM>>>(H1, HID, W_hh, b_hh, GH2, NN, HID);
    // 4. h2 per edge
    h2_kernel<<<NE, HID>>>(emi);
    // 5. GH3 = h2 @ W_hh^T + b_hh        (per edge — the big one)
    tc_gemm2<<<dim3(gx, (NE + BM - 1) / BM), 256, GEMM_SMEM>>>(h2, HID, W_hh, b_hh, GH3, NE, HID);
    // 6+7. h3 per edge fused with attention logits + segment max
    h3_attn_kernel<<<NE, HID>>>(emi, attn, edge_dst);
    // 8-9. softmax denom + weighted aggregation
    expsum_kernel<<<(NE * NH + 255) / 256, 256>>>(edge_dst);
    agg_kernel<<<NE, HID>>>(edge_dst, out);
}